// round 1
// baseline (speedup 1.0000x reference)
#include <cuda_runtime.h>

#define NH    16
#define DK    64
#define BATCH 2
#define SEQ   2048
#define DEMB  1024
#define MTOT  (BATCH*SEQ)   // 4096

// Scratch (allocation-free: device globals)
__device__ float g_Q[BATCH*NH*SEQ*DK];   // [b,h,s,dk]
__device__ float g_K[BATCH*NH*SEQ*DK];   // [b,h,s,dk]
__device__ float g_V[BATCH*NH*SEQ*DK];   // [b,h,s,dk]
__device__ float g_C[MTOT*DEMB];         // ctx, [b,s,h,dk] == row-major [4096,1024]

// ---------------------------------------------------------------------------
// C = A (M x K) * B^T  where B is [N x K] row-major (torch Linear weight).
// MODE 0: C row-major [M x DEMB]     (output projection)
// MODE 1: scatter to [b,h,s,dk]      (Q/K/V projections), scaled by cscale
// Tiles: 128x128x8, 256 threads, 8x8 per-thread microtile.
// ---------------------------------------------------------------------------
template<int MODE>
__global__ void __launch_bounds__(256) gemm_kernel(const float* __restrict__ A,
                                                   const float* __restrict__ Bm,
                                                   float* __restrict__ C,
                                                   float cscale)
{
    __shared__ float As[8][128];
    __shared__ float Bs[8][128];
    const int tid = threadIdx.x;
    const int n0 = blockIdx.x * 128;
    const int m0 = blockIdx.y * 128;
    const int lr = tid >> 1;           // 0..127
    const int lc = (tid & 1) << 2;     // 0 or 4
    const int tx = tid & 15;
    const int ty = tid >> 4;

    float acc[8][8];
#pragma unroll
    for (int i = 0; i < 8; i++)
#pragma unroll
        for (int j = 0; j < 8; j++) acc[i][j] = 0.f;

    const float* Ap = A  + (m0 + lr) * DEMB + lc;
    const float* Bp = Bm + (n0 + lr) * DEMB + lc;

    for (int k0 = 0; k0 < DEMB; k0 += 8) {
        float4 av = *(const float4*)(Ap + k0);
        float4 bv = *(const float4*)(Bp + k0);
        As[lc+0][lr] = av.x; As[lc+1][lr] = av.y; As[lc+2][lr] = av.z; As[lc+3][lr] = av.w;
        Bs[lc+0][lr] = bv.x; Bs[lc+1][lr] = bv.y; Bs[lc+2][lr] = bv.z; Bs[lc+3][lr] = bv.w;
        __syncthreads();
#pragma unroll
        for (int kk = 0; kk < 8; kk++) {
            float a[8], b[8];
            *(float4*)&a[0] = *(const float4*)&As[kk][ty*8];
            *(float4*)&a[4] = *(const float4*)&As[kk][ty*8+4];
            *(float4*)&b[0] = *(const float4*)&Bs[kk][tx*8];
            *(float4*)&b[4] = *(const float4*)&Bs[kk][tx*8+4];
#pragma unroll
            for (int i = 0; i < 8; i++)
#pragma unroll
                for (int j = 0; j < 8; j++)
                    acc[i][j] = fmaf(a[i], b[j], acc[i][j]);
        }
        __syncthreads();
    }

#pragma unroll
    for (int i = 0; i < 8; i++) {
        const int m = m0 + ty*8 + i;
        if (MODE == 0) {
            float* Cp = C + m*DEMB + n0 + tx*8;
            float4 v0 = make_float4(acc[i][0]*cscale, acc[i][1]*cscale,
                                    acc[i][2]*cscale, acc[i][3]*cscale);
            float4 v1 = make_float4(acc[i][4]*cscale, acc[i][5]*cscale,
                                    acc[i][6]*cscale, acc[i][7]*cscale);
            *(float4*)Cp       = v0;
            *(float4*)(Cp + 4) = v1;
        } else {
            const int bb = m >> 11;          // m / SEQ
            const int s  = m & (SEQ - 1);
#pragma unroll
            for (int j = 0; j < 8; j++) {
                const int nn = n0 + tx*8 + j;
                const int h  = nn >> 6;
                const int dk = nn & 63;
                C[(((bb*NH + h)*SEQ + s) << 6) + dk] = acc[i][j] * cscale;
            }
        }
    }
}

// ---------------------------------------------------------------------------
// Fused attention per (b,h): 128-query x 128-key tiles over S=2048.
// Scores are clipped to [-5,5] BEFORE softmax => exp is bounded, no online max.
// ctx written to g_C in [b,s,h,dk] layout (row-major A for output projection).
// Thread map (tx=tid&15, ty=tid>>4):
//   score phase: q = tx+16*qi (8), k = ty+16*ki (8)   -> 8x8 micro (1B/FMA)
//   AV phase:    q = tx+16*qi (8), d = ty*4+di (4)    -> 8x4 micro
// ---------------------------------------------------------------------------
#define ATTN_SMEM ((64*130 + 128*64 + 128*130) * 4)

__global__ void __launch_bounds__(256) attn_kernel()
{
    extern __shared__ float sm[];
    float* Qs  = sm;                        // [d][q] 64 x (128+2) transposed
    float* KVs = sm + 64*130;               // [k][d] 128 x 64  (K, then V)
    float* Ps  = sm + 64*130 + 128*64;      // [q][k] 128 x (128+2)

    const int tid = threadIdx.x;
    const int tx = tid & 15;
    const int ty = tid >> 4;
    const int bh = blockIdx.y;              // b*NH + h
    const int q0 = blockIdx.x << 7;

    const float* Qg = g_Q + bh * (SEQ*DK);
    const float* Kg = g_K + bh * (SEQ*DK);
    const float* Vg = g_V + bh * (SEQ*DK);

    // Load Q tile (128 x 64) transposed into Qs[d][q]
#pragma unroll
    for (int i = 0; i < 8; i++) {
        int f   = tid + 256*i;              // float4 index 0..2047
        int row = f >> 4;                   // 0..127
        int c4  = (f & 15) << 2;            // 0..60
        float4 v = *(const float4*)&Qg[(q0 + row)*DK + c4];
        Qs[(c4+0)*130 + row] = v.x;
        Qs[(c4+1)*130 + row] = v.y;
        Qs[(c4+2)*130 + row] = v.z;
        Qs[(c4+3)*130 + row] = v.w;
    }

    float acc[8][4];
    float rsum[8];
#pragma unroll
    for (int qi = 0; qi < 8; qi++) {
        rsum[qi] = 0.f;
#pragma unroll
        for (int di = 0; di < 4; di++) acc[qi][di] = 0.f;
    }

    __syncthreads();

    for (int kt = 0; kt < SEQ/128; kt++) {
        // ---- load K tile (natural [k][d], float4, conflict-free) ----
        const float* Kt = Kg + (kt << 7) * DK;
#pragma unroll
        for (int i = 0; i < 8; i++) {
            int f = tid + 256*i;
            *(float4*)&KVs[f << 2] = *(const float4*)&Kt[f << 2];
        }
        __syncthreads();

        // ---- scores: sc[qi][ki] = Q[q,:] . K[k,:]  (Q pre-scaled by 1/8) ----
        float sc[8][8];
#pragma unroll
        for (int qi = 0; qi < 8; qi++)
#pragma unroll
            for (int ki = 0; ki < 8; ki++) sc[qi][ki] = 0.f;

#pragma unroll 4
        for (int d = 0; d < 64; d++) {
            float aq[8], bk[8];
#pragma unroll
            for (int qi = 0; qi < 8; qi++) aq[qi] = Qs[d*130 + tx + 16*qi];
#pragma unroll
            for (int ki = 0; ki < 8; ki++) bk[ki] = KVs[(ty + 16*ki)*64 + d];
#pragma unroll
            for (int qi = 0; qi < 8; qi++)
#pragma unroll
                for (int ki = 0; ki < 8; ki++)
                    sc[qi][ki] = fmaf(aq[qi], bk[ki], sc[qi][ki]);
        }

        // ---- clip + exp, stage P in smem ----
#pragma unroll
        for (int qi = 0; qi < 8; qi++)
#pragma unroll
            for (int ki = 0; ki < 8; ki++) {
                float v = fminf(fmaxf(sc[qi][ki], -5.f), 5.f);
                Ps[(tx + 16*qi)*130 + ty + 16*ki] = __expf(v);
            }
        __syncthreads();

        // ---- load V tile over K's buffer ----
        const float* Vt = Vg + (kt << 7) * DK;
#pragma unroll
        for (int i = 0; i < 8; i++) {
            int f = tid + 256*i;
            *(float4*)&KVs[f << 2] = *(const float4*)&Vt[f << 2];
        }
        __syncthreads();

        // ---- AV: ctx[q][d] += P[q][k] * V[k][d]; rsum[q] += P[q][k] ----
#pragma unroll 2
        for (int k = 0; k < 128; k++) {
            float pv[8];
#pragma unroll
            for (int qi = 0; qi < 8; qi++) pv[qi] = Ps[(tx + 16*qi)*130 + k];
            float4 vv = *(const float4*)&KVs[k*64 + ty*4];
#pragma unroll
            for (int qi = 0; qi < 8; qi++) {
                rsum[qi] += pv[qi];
                acc[qi][0] = fmaf(pv[qi], vv.x, acc[qi][0]);
                acc[qi][1] = fmaf(pv[qi], vv.y, acc[qi][1]);
                acc[qi][2] = fmaf(pv[qi], vv.z, acc[qi][2]);
                acc[qi][3] = fmaf(pv[qi], vv.w, acc[qi][3]);
            }
        }
        __syncthreads();
    }

    // ---- normalize + write ctx in [b,s,h,dk] layout ----
    const int bb = bh >> 4;
    const int h  = bh & 15;
#pragma unroll
    for (int qi = 0; qi < 8; qi++) {
        const int s = q0 + tx + 16*qi;
        const float inv = 1.f / rsum[qi];
        float4 o = make_float4(acc[qi][0]*inv, acc[qi][1]*inv,
                               acc[qi][2]*inv, acc[qi][3]*inv);
        *(float4*)&g_C[(((bb*SEQ + s)*NH + h) << 6) + ty*4] = o;
    }
}

// ---------------------------------------------------------------------------
extern "C" void kernel_launch(void* const* d_in, const int* in_sizes, int n_in,
                              void* d_out, int out_size)
{
    const float* X  = (const float*)d_in[0];   // n  [2,2048,1024]
    const float* Wq = (const float*)d_in[1];
    const float* Wk = (const float*)d_in[2];
    const float* Wv = (const float*)d_in[3];
    const float* Wo = (const float*)d_in[4];
    float* out = (float*)d_out;

    float *pQ, *pK, *pV, *pC;
    cudaGetSymbolAddress((void**)&pQ, g_Q);
    cudaGetSymbolAddress((void**)&pK, g_K);
    cudaGetSymbolAddress((void**)&pV, g_V);
    cudaGetSymbolAddress((void**)&pC, g_C);

    cudaFuncSetAttribute(attn_kernel,
                         cudaFuncAttributeMaxDynamicSharedMemorySize, ATTN_SMEM);

    dim3 gg(DEMB/128, MTOT/128);
    // Q projection carries the 1/sqrt(Dk) = 0.125 scale
    gemm_kernel<1><<<gg, 256>>>(X, Wq, pQ, 0.125f);
    gemm_kernel<1><<<gg, 256>>>(X, Wk, pK, 1.0f);
    gemm_kernel<1><<<gg, 256>>>(X, Wv, pV, 1.0f);

    attn_kernel<<<dim3(SEQ/128, BATCH*NH), 256, ATTN_SMEM>>>();

    gemm_kernel<0><<<gg, 256>>>(pC, Wo, out, 1.0f);
}

// round 4
// speedup vs baseline: 1.4856x; 1.4856x over previous
#include <cuda_runtime.h>
#include <cstdint>

#define NH    16
#define DK    64
#define BATCH 2
#define SEQ   2048
#define DEMB  1024
#define MTOT  (BATCH*SEQ)   // 4096

// Scratch (allocation-free: device globals)
__device__ float g_Q[BATCH*NH*SEQ*DK];   // [b,h,s,dk], pre-scaled by 0.125*log2(e)
__device__ float g_K[BATCH*NH*SEQ*DK];
__device__ float g_V[BATCH*NH*SEQ*DK];
__device__ float g_C[MTOT*DEMB];         // ctx, [b,s,h,dk] == row-major [4096,1024]

// ---------------------------------------------------------------------------
// helpers
// ---------------------------------------------------------------------------
__device__ __forceinline__ uint32_t smem_u32(const void* p) {
    uint32_t a;
    asm("{ .reg .u64 t; cvta.to.shared.u64 t, %1; cvt.u32.u64 %0, t; }"
        : "=r"(a) : "l"(p));
    return a;
}
__device__ __forceinline__ void cp16(uint32_t dst, const void* src) {
    asm volatile("cp.async.cg.shared.global [%0], [%1], 16;"
                 :: "r"(dst), "l"(src) : "memory");
}
#define CP_COMMIT() asm volatile("cp.async.commit_group;" ::: "memory")
#define CP_WAIT(n)  asm volatile("cp.async.wait_group %0;" :: "n"(n) : "memory")

// packed f32x2 (Blackwell base ISA)
#define PACK2(d, lo, hi)  asm("mov.b64 %0, {%1, %2};" : "=l"(d) : "f"(lo), "f"(hi))
#define UNPK2(lo, hi, s)  asm("mov.b64 {%0, %1}, %2;" : "=f"(lo), "=f"(hi) : "l"(s))
#define FMA2(d, a, b, c)  asm("fma.rn.f32x2 %0, %1, %2, %3;" \
                              : "=l"(d) : "l"(a), "l"(b), "l"(c))

__device__ __forceinline__ float ex2f(float x) {
    float r; asm("ex2.approx.ftz.f32 %0, %1;" : "=f"(r) : "f"(x)); return r;
}
__device__ __forceinline__ uint32_t cvt_tf32(float x) {
    uint32_t r; asm("cvt.rna.tf32.f32 %0, %1;" : "=r"(r) : "f"(x)); return r;
}
__device__ __forceinline__ void mma_tf32(float* d, const uint32_t* a, const uint32_t* b) {
    asm volatile("mma.sync.aligned.m16n8k8.row.col.f32.tf32.tf32.f32 "
        "{%0,%1,%2,%3}, {%4,%5,%6,%7}, {%8,%9}, {%0,%1,%2,%3};"
        : "+f"(d[0]), "+f"(d[1]), "+f"(d[2]), "+f"(d[3])
        : "r"(a[0]), "r"(a[1]), "r"(a[2]), "r"(a[3]), "r"(b[0]), "r"(b[1]));
}

// ===========================================================================
// tf32 mma.sync GEMM:  C = A (M x 1024) * B^T,  B is [N x 1024] row-major.
// CTA 128x128, 4 warps (2x2 of 64x64), K chunks of 32, cp.async 2-stage.
// MODE 0: C row-major [M x DEMB]; MODE 1: scatter to [b,h,s,dk], scaled.
// ===========================================================================
#define GPAD 36
#define GSTAGE (2 * 128 * GPAD)              // floats per stage (A+B) = 9216
#define GSMEM  (2 * GSTAGE * 4)              // 73728 bytes

template<int MODE>
__global__ void __launch_bounds__(128) gemm_tc(const float* __restrict__ A,
                                               const float* __restrict__ Bm,
                                               float* __restrict__ C,
                                               float cscale)
{
    extern __shared__ float gs[];
    const int tid  = threadIdx.x;
    const int lane = tid & 31;
    const int wid  = tid >> 5;
    const int wm   = (wid & 1) * 64;
    const int wn   = (wid >> 1) * 64;
    const int m0   = blockIdx.y * 128;
    const int n0   = blockIdx.x * 128;
    const uint32_t sb = smem_u32(gs);

#define STAGE_LOAD(cc, ss) do {                                              \
    _Pragma("unroll")                                                        \
    for (int i = 0; i < 16; i++) {                                           \
        int f   = tid + 128 * i;            /* 0..2047 */                    \
        int isB = f >> 10;                                                   \
        int g   = f & 1023;                                                  \
        int row = g >> 3;                                                    \
        int cir = g & 7;                                                     \
        const float* src = (isB ? Bm + (size_t)(n0 + row) * DEMB             \
                                : A  + (size_t)(m0 + row) * DEMB)            \
                           + (cc) * 32 + cir * 4;                            \
        uint32_t dst = sb + ((ss) * GSTAGE + isB * (128 * GPAD)              \
                             + row * GPAD) * 4 + cir * 16;                   \
        cp16(dst, src);                                                      \
    }                                                                        \
} while (0)

    STAGE_LOAD(0, 0); CP_COMMIT();
    STAGE_LOAD(1, 1); CP_COMMIT();

    float acc[4][8][4];
#pragma unroll
    for (int mi = 0; mi < 4; mi++)
#pragma unroll
        for (int ni = 0; ni < 8; ni++)
#pragma unroll
            for (int j = 0; j < 4; j++) acc[mi][ni][j] = 0.f;

    const int r4 = lane >> 2;
    const int c4 = lane & 3;

    for (int c = 0; c < 32; c++) {
        CP_WAIT(1);
        __syncthreads();
        const float* As = gs + (c & 1) * GSTAGE;
        const float* Bs = As + 128 * GPAD;

#pragma unroll
        for (int k8 = 0; k8 < 4; k8++) {
            const int kb = k8 * 8 + c4;
            uint32_t a[4][4], b[8][2];
#pragma unroll
            for (int mi = 0; mi < 4; mi++) {
                const int r = wm + mi * 16 + r4;
                a[mi][0] = cvt_tf32(As[r * GPAD + kb]);
                a[mi][1] = cvt_tf32(As[(r + 8) * GPAD + kb]);
                a[mi][2] = cvt_tf32(As[r * GPAD + kb + 4]);
                a[mi][3] = cvt_tf32(As[(r + 8) * GPAD + kb + 4]);
            }
#pragma unroll
            for (int ni = 0; ni < 8; ni++) {
                const int cn = wn + ni * 8 + r4;
                b[ni][0] = cvt_tf32(Bs[cn * GPAD + kb]);
                b[ni][1] = cvt_tf32(Bs[cn * GPAD + kb + 4]);
            }
#pragma unroll
            for (int mi = 0; mi < 4; mi++)
#pragma unroll
                for (int ni = 0; ni < 8; ni++)
                    mma_tf32(acc[mi][ni], a[mi], b[ni]);
        }
        __syncthreads();
        if (c + 2 < 32) STAGE_LOAD(c + 2, c & 1);
        CP_COMMIT();
    }

    // ---- epilogue ----
    const int c2 = (lane & 3) * 2;
#pragma unroll
    for (int mi = 0; mi < 4; mi++) {
#pragma unroll
        for (int ni = 0; ni < 8; ni++) {
            const int m = m0 + wm + mi * 16 + r4;
            const int n = n0 + wn + ni * 8 + c2;
#pragma unroll
            for (int half = 0; half < 2; half++) {
                const int mm = m + half * 8;
                float2 v = make_float2(acc[mi][ni][2*half]   * cscale,
                                       acc[mi][ni][2*half+1] * cscale);
                if (MODE == 0) {
                    *(float2*)&C[(size_t)mm * DEMB + n] = v;
                } else {
                    const int b  = mm >> 11;
                    const int s  = mm & (SEQ - 1);
                    const int h  = n >> 6;
                    const int dk = n & 63;
                    *(float2*)&C[(((size_t)(b * NH + h) * SEQ + s) << 6) + dk] = v;
                }
            }
        }
    }
#undef STAGE_LOAD
}

// ===========================================================================
// Fused attention, fp32 math via packed f32x2 FMA.
// Per (b,h): 128q x 128k tiles. Scores pre-multiplied by log2(e)/8 (folded
// into Q projection), clipped at +-5*log2(e), exponentiated with ex2.approx.
// P stored TRANSPOSED [k][q] in smem (conflict-free store AND load).
// rsum: per-thread partials over own k-slice during score phase, then a
// one-time 16-way cross-ty smem reduction at the end (round-3 bug fix).
// K/V tiles prefetched with cp.async (K double-buffered).
// ===========================================================================
#define CLIP2 7.2134752044448169f            // 5 * log2(e)
// smem map (floats): Qs [64][129] | Ks0 [128][64] | Ks1 | Vs [128][64] | Ps [128][128]
#define OFF_KS0 8256
#define OFF_KS1 16448
#define OFF_VS  24640
#define OFF_PS  32832
#define ATTN_SMEM ((OFF_PS + 128*128) * 4)   // 196864 bytes

__global__ void __launch_bounds__(256, 1) attn_kernel()
{
    extern __shared__ float smf[];
    float* Qs = smf;
    float* Vs = smf + OFF_VS;
    float* Ps = smf + OFF_PS;
    const uint32_t sb = smem_u32(smf);
    const uint32_t ksAddr[2] = { sb + OFF_KS0 * 4, sb + OFF_KS1 * 4 };
    const uint32_t vsAddr = sb + OFF_VS * 4;

    const int tid = threadIdx.x;
    const int tx  = tid & 15;
    const int ty  = tid >> 4;
    const int bh  = blockIdx.y;
    const int q0  = blockIdx.x << 7;

    const float* Qg = g_Q + (size_t)bh * (SEQ * DK);
    const float* Kg = g_K + (size_t)bh * (SEQ * DK);
    const float* Vg = g_V + (size_t)bh * (SEQ * DK);

    // prefetch K tile 0
#pragma unroll
    for (int i = 0; i < 8; i++) {
        int f = tid + 256 * i;
        cp16(ksAddr[0] + f * 16, (const char*)Kg + f * 16);
    }
    CP_COMMIT();

    // load Q tile transposed: Qs[d][q], stride 129
#pragma unroll
    for (int i = 0; i < 8; i++) {
        int f   = tid + 256 * i;
        int row = f >> 4;
        int c4v = (f & 15) << 2;
        float4 v = *(const float4*)&Qg[(size_t)(q0 + row) * DK + c4v];
        Qs[(c4v + 0) * 129 + row] = v.x;
        Qs[(c4v + 1) * 129 + row] = v.y;
        Qs[(c4v + 2) * 129 + row] = v.z;
        Qs[(c4v + 3) * 129 + row] = v.w;
    }

    float rsum[8];                    // partial: only this thread's k-slice
    unsigned long long acc2[8][2];
#pragma unroll
    for (int qi = 0; qi < 8; qi++) {
        rsum[qi] = 0.f;
        acc2[qi][0] = 0ull; acc2[qi][1] = 0ull;
    }

    for (int t = 0; t < SEQ / 128; t++) {
        // prefetch V_t
        const char* Vt = (const char*)(Vg + (size_t)(t << 7) * DK);
#pragma unroll
        for (int i = 0; i < 8; i++) {
            int f = tid + 256 * i;
            cp16(vsAddr + f * 16, Vt + f * 16);
        }
        CP_COMMIT();
        // prefetch K_{t+1}
        if (t + 1 < SEQ / 128) {
            const char* Kt = (const char*)(Kg + (size_t)((t + 1) << 7) * DK);
#pragma unroll
            for (int i = 0; i < 8; i++) {
                int f = tid + 256 * i;
                cp16(ksAddr[(t + 1) & 1] + f * 16, Kt + f * 16);
            }
        }
        CP_COMMIT();

        CP_WAIT(2);               // K_t resident
        __syncthreads();

        const float* Kb = smf + (((t & 1) == 0) ? OFF_KS0 : OFF_KS1);

        // ---- scores: sc2[qi][kj] over (k = ty+32kj, ty+16+32kj) ----
        unsigned long long sc2[8][4];
#pragma unroll
        for (int qi = 0; qi < 8; qi++)
#pragma unroll
            for (int kj = 0; kj < 4; kj++) sc2[qi][kj] = 0ull;

#pragma unroll 2
        for (int d = 0; d < 64; d++) {
            float aq[8], bk[8];
#pragma unroll
            for (int qi = 0; qi < 8; qi++) aq[qi] = Qs[d * 129 + tx + 16 * qi];
#pragma unroll
            for (int ki = 0; ki < 8; ki++) bk[ki] = Kb[(ty + 16 * ki) * 64 + d];
            unsigned long long aqd[8], bkp[4];
#pragma unroll
            for (int qi = 0; qi < 8; qi++) PACK2(aqd[qi], aq[qi], aq[qi]);
#pragma unroll
            for (int kj = 0; kj < 4; kj++) PACK2(bkp[kj], bk[2*kj], bk[2*kj+1]);
#pragma unroll
            for (int qi = 0; qi < 8; qi++)
#pragma unroll
                for (int kj = 0; kj < 4; kj++)
                    FMA2(sc2[qi][kj], aqd[qi], bkp[kj], sc2[qi][kj]);
        }

        // ---- clip + 2^x, store P transposed [k][q], accumulate partial rsum ----
#pragma unroll
        for (int qi = 0; qi < 8; qi++) {
            float rs = 0.f;
#pragma unroll
            for (int kj = 0; kj < 4; kj++) {
                float s0, s1;
                UNPK2(s0, s1, sc2[qi][kj]);
                s0 = fminf(fmaxf(s0, -CLIP2), CLIP2);
                s1 = fminf(fmaxf(s1, -CLIP2), CLIP2);
                float e0 = ex2f(s0), e1 = ex2f(s1);
                rs += e0 + e1;
                Ps[(ty +      32 * kj) * 128 + tx + 16 * qi] = e0;
                Ps[(ty + 16 + 32 * kj) * 128 + tx + 16 * qi] = e1;
            }
            rsum[qi] += rs;
        }

        CP_WAIT(1);               // V_t resident
        __syncthreads();          // P + V visible

        // ---- AV: acc[q][d] += P[k][q] * V[k][d] ----
#pragma unroll 2
        for (int k = 0; k < 128; k++) {
            float pv[8];
#pragma unroll
            for (int qi = 0; qi < 8; qi++) pv[qi] = Ps[k * 128 + tx + 16 * qi];
            float4 vv = *(const float4*)&Vs[k * 64 + ty * 4];
            unsigned long long v01, v23, pvd;
            PACK2(v01, vv.x, vv.y);
            PACK2(v23, vv.z, vv.w);
#pragma unroll
            for (int qi = 0; qi < 8; qi++) {
                PACK2(pvd, pv[qi], pv[qi]);
                FMA2(acc2[qi][0], pvd, v01, acc2[qi][0]);
                FMA2(acc2[qi][1], pvd, v23, acc2[qi][1]);
            }
        }
        __syncthreads();          // Ps / V free for next tile
    }

    // ---- cross-ty reduction of rsum partials (16 threads share each q) ----
    float* Rs = Ps;               // reuse Ps as [128][17] scratch
#pragma unroll
    for (int qi = 0; qi < 8; qi++)
        Rs[(tx + 16 * qi) * 17 + ty] = rsum[qi];
    __syncthreads();

    // ---- normalize + write ctx in [b,s,h,dk] layout ----
    const int bb = bh >> 4;
    const int h  = bh & 15;
#pragma unroll
    for (int qi = 0; qi < 8; qi++) {
        const int s = q0 + tx + 16 * qi;
        const float* rp = &Rs[(tx + 16 * qi) * 17];
        float tot = 0.f;
#pragma unroll
        for (int j = 0; j < 16; j++) tot += rp[j];
        const float inv = 1.f / tot;
        float o0, o1, o2, o3;
        UNPK2(o0, o1, acc2[qi][0]);
        UNPK2(o2, o3, acc2[qi][1]);
        float4 o = make_float4(o0 * inv, o1 * inv, o2 * inv, o3 * inv);
        *(float4*)&g_C[(((size_t)(bb * SEQ + s) * NH + h) << 6) + ty * 4] = o;
    }
}

// ===========================================================================
extern "C" void kernel_launch(void* const* d_in, const int* in_sizes, int n_in,
                              void* d_out, int out_size)
{
    const float* X  = (const float*)d_in[0];
    const float* Wq = (const float*)d_in[1];
    const float* Wk = (const float*)d_in[2];
    const float* Wv = (const float*)d_in[3];
    const float* Wo = (const float*)d_in[4];
    float* out = (float*)d_out;

    float *pQ, *pK, *pV, *pC;
    cudaGetSymbolAddress((void**)&pQ, g_Q);
    cudaGetSymbolAddress((void**)&pK, g_K);
    cudaGetSymbolAddress((void**)&pV, g_V);
    cudaGetSymbolAddress((void**)&pC, g_C);

    cudaFuncSetAttribute(gemm_tc<0>, cudaFuncAttributeMaxDynamicSharedMemorySize, GSMEM);
    cudaFuncSetAttribute(gemm_tc<1>, cudaFuncAttributeMaxDynamicSharedMemorySize, GSMEM);
    cudaFuncSetAttribute(attn_kernel, cudaFuncAttributeMaxDynamicSharedMemorySize, ATTN_SMEM);

    dim3 gg(DEMB / 128, MTOT / 128);   // (8, 32)
    // Q projection carries 1/sqrt(Dk) * log2(e) so attention can use ex2
    gemm_tc<1><<<gg, 128, GSMEM>>>(X, Wq, pQ, 0.18033688011112042592f);
    gemm_tc<1><<<gg, 128, GSMEM>>>(X, Wk, pK, 1.0f);
    gemm_tc<1><<<gg, 128, GSMEM>>>(X, Wv, pV, 1.0f);

    attn_kernel<<<dim3(SEQ / 128, BATCH * NH), 256, ATTN_SMEM>>>();

    gemm_tc<0><<<gg, 128, GSMEM>>>(pC, Wo, out, 1.0f);
}

// round 6
// speedup vs baseline: 3.3296x; 2.2412x over previous
#include <cuda_runtime.h>
#include <cstdint>

#define NH    16
#define DK    64
#define BATCH 2
#define SEQ   2048
#define DEMB  1024
#define MTOT  (BATCH*SEQ)   // 4096

// Scratch (allocation-free: device globals)
__device__ float g_Q[BATCH*NH*SEQ*DK];   // [b,h,s,dk], pre-scaled by 0.125*log2(e)
__device__ float g_K[BATCH*NH*SEQ*DK];
__device__ float g_V[BATCH*NH*SEQ*DK];
__device__ float g_C[MTOT*DEMB];         // ctx, [b,s,h,dk] == row-major [4096,1024]

// ---------------------------------------------------------------------------
// helpers
// ---------------------------------------------------------------------------
__device__ __forceinline__ uint32_t smem_u32(const void* p) {
    uint32_t a;
    asm("{ .reg .u64 t; cvta.to.shared.u64 t, %1; cvt.u32.u64 %0, t; }"
        : "=r"(a) : "l"(p));
    return a;
}
__device__ __forceinline__ void cp16(uint32_t dst, const void* src) {
    asm volatile("cp.async.cg.shared.global [%0], [%1], 16;"
                 :: "r"(dst), "l"(src) : "memory");
}
#define CP_COMMIT() asm volatile("cp.async.commit_group;" ::: "memory")
#define CP_WAIT(n)  asm volatile("cp.async.wait_group %0;" :: "n"(n) : "memory")

__device__ __forceinline__ float ex2f(float x) {
    float r; asm("ex2.approx.ftz.f32 %0, %1;" : "=f"(r) : "f"(x)); return r;
}
__device__ __forceinline__ uint32_t cvt_tf32(float x) {
    uint32_t r; asm("cvt.rna.tf32.f32 %0, %1;" : "=r"(r) : "f"(x)); return r;
}
__device__ __forceinline__ void mma_tf32(float* d, const uint32_t* a, const uint32_t* b) {
    asm volatile("mma.sync.aligned.m16n8k8.row.col.f32.tf32.tf32.f32 "
        "{%0,%1,%2,%3}, {%4,%5,%6,%7}, {%8,%9}, {%0,%1,%2,%3};"
        : "+f"(d[0]), "+f"(d[1]), "+f"(d[2]), "+f"(d[3])
        : "r"(a[0]), "r"(a[1]), "r"(a[2]), "r"(a[3]), "r"(b[0]), "r"(b[1]));
}

// ===========================================================================
// tf32 mma.sync GEMM (unchanged; measured 4.6e-4 total, ~75us each)
// ===========================================================================
#define GPAD 36
#define GSTAGE (2 * 128 * GPAD)
#define GSMEM  (2 * GSTAGE * 4)

template<int MODE>
__global__ void __launch_bounds__(128) gemm_tc(const float* __restrict__ A,
                                               const float* __restrict__ Bm,
                                               float* __restrict__ C,
                                               float cscale)
{
    extern __shared__ float gs[];
    const int tid  = threadIdx.x;
    const int lane = tid & 31;
    const int wid  = tid >> 5;
    const int wm   = (wid & 1) * 64;
    const int wn   = (wid >> 1) * 64;
    const int m0   = blockIdx.y * 128;
    const int n0   = blockIdx.x * 128;
    const uint32_t sb = smem_u32(gs);

#define STAGE_LOAD(cc, ss) do {                                              \
    _Pragma("unroll")                                                        \
    for (int i = 0; i < 16; i++) {                                           \
        int f   = tid + 128 * i;                                             \
        int isB = f >> 10;                                                   \
        int g   = f & 1023;                                                  \
        int row = g >> 3;                                                    \
        int cir = g & 7;                                                     \
        const float* src = (isB ? Bm + (size_t)(n0 + row) * DEMB             \
                                : A  + (size_t)(m0 + row) * DEMB)            \
                           + (cc) * 32 + cir * 4;                            \
        uint32_t dst = sb + ((ss) * GSTAGE + isB * (128 * GPAD)              \
                             + row * GPAD) * 4 + cir * 16;                   \
        cp16(dst, src);                                                      \
    }                                                                        \
} while (0)

    STAGE_LOAD(0, 0); CP_COMMIT();
    STAGE_LOAD(1, 1); CP_COMMIT();

    float acc[4][8][4];
#pragma unroll
    for (int mi = 0; mi < 4; mi++)
#pragma unroll
        for (int ni = 0; ni < 8; ni++)
#pragma unroll
            for (int j = 0; j < 4; j++) acc[mi][ni][j] = 0.f;

    const int r4 = lane >> 2;
    const int c4 = lane & 3;

    for (int c = 0; c < 32; c++) {
        CP_WAIT(1);
        __syncthreads();
        const float* As = gs + (c & 1) * GSTAGE;
        const float* Bs = As + 128 * GPAD;

#pragma unroll
        for (int k8 = 0; k8 < 4; k8++) {
            const int kb = k8 * 8 + c4;
            uint32_t a[4][4], b[8][2];
#pragma unroll
            for (int mi = 0; mi < 4; mi++) {
                const int r = wm + mi * 16 + r4;
                a[mi][0] = cvt_tf32(As[r * GPAD + kb]);
                a[mi][1] = cvt_tf32(As[(r + 8) * GPAD + kb]);
                a[mi][2] = cvt_tf32(As[r * GPAD + kb + 4]);
                a[mi][3] = cvt_tf32(As[(r + 8) * GPAD + kb + 4]);
            }
#pragma unroll
            for (int ni = 0; ni < 8; ni++) {
                const int cn = wn + ni * 8 + r4;
                b[ni][0] = cvt_tf32(Bs[cn * GPAD + kb]);
                b[ni][1] = cvt_tf32(Bs[cn * GPAD + kb + 4]);
            }
#pragma unroll
            for (int mi = 0; mi < 4; mi++)
#pragma unroll
                for (int ni = 0; ni < 8; ni++)
                    mma_tf32(acc[mi][ni], a[mi], b[ni]);
        }
        __syncthreads();
        if (c + 2 < 32) STAGE_LOAD(c + 2, c & 1);
        CP_COMMIT();
    }

    const int c2 = (lane & 3) * 2;
#pragma unroll
    for (int mi = 0; mi < 4; mi++) {
#pragma unroll
        for (int ni = 0; ni < 8; ni++) {
            const int m = m0 + wm + mi * 16 + r4;
            const int n = n0 + wn + ni * 8 + c2;
#pragma unroll
            for (int half = 0; half < 2; half++) {
                const int mm = m + half * 8;
                float2 v = make_float2(acc[mi][ni][2*half]   * cscale,
                                       acc[mi][ni][2*half+1] * cscale);
                if (MODE == 0) {
                    *(float2*)&C[(size_t)mm * DEMB + n] = v;
                } else {
                    const int b  = mm >> 11;
                    const int s  = mm & (SEQ - 1);
                    const int h  = n >> 6;
                    const int dk = n & 63;
                    *(float2*)&C[(((size_t)(b * NH + h) * SEQ + s) << 6) + dk] = v;
                }
            }
        }
    }
#undef STAGE_LOAD
}

// ===========================================================================
// Tensor-core attention (mma.sync tf32).
// CTA: 256 thr / 8 warps, q-tile 128 (warp = m16). k tiles of 128 over S.
// Q,K smem row-major pad 68; V row-major pad 72; P row-major pad 132
// (128-wide matrix! round-5 bug was stride 68 here -> smem OOB).
// 132 % 32 == 4 => A-frag loads P[g*132+tq+..] hit banks 4g+tq (bijective,
// conflict-free). Scores clipped & exponentiated in C-fragments (ex2, log2e
// folded into Q), P staged via warp-private smem rows, AV on tensor pipe.
// rsum: per-thread partials + quad shfl.bfly reduce at the end.
// ===========================================================================
#define CLIP2 7.2134752044448169f            // 5 * log2(e)
#define PK 68
#define PV 72
#define PP 132
#define AOFF_Q  0
#define AOFF_K0 (128*PK)                     // 8704
#define AOFF_K1 (2*128*PK)                   // 17408
#define AOFF_V  (3*128*PK)                   // 26112
#define AOFF_P  (3*128*PK + 128*PV)          // 35328
#define ATT_SMEM ((AOFF_P + 128*PP)*4)       // 208896 bytes

__global__ void __launch_bounds__(256, 1) attn_tc()
{
    extern __shared__ float smf[];
    const uint32_t sb = smem_u32(smf);
    const int tid  = threadIdx.x;
    const int wid  = tid >> 5;
    const int lane = tid & 31;
    const int g    = lane >> 2;        // row-in-8 group
    const int tq   = lane & 3;         // quad index
    const int bh   = blockIdx.y;
    const int q0   = blockIdx.x << 7;

    const float* Qg = g_Q + (size_t)bh * (SEQ * DK) + (size_t)q0 * DK;
    const float* Kg = g_K + (size_t)bh * (SEQ * DK);
    const float* Vg = g_V + (size_t)bh * (SEQ * DK);

    // async-load Q tile and K tile 0 (one group)
#pragma unroll
    for (int i = 0; i < 8; i++) {
        int f = tid + 256 * i;
        int r = f >> 4;
        int c = (f & 15) << 2;
        cp16(sb + (AOFF_Q  + r * PK + c) * 4, Qg + (size_t)r * DK + c);
        cp16(sb + (AOFF_K0 + r * PK + c) * 4, Kg + (size_t)r * DK + c);
    }
    CP_COMMIT();

    float acc[8][4];
#pragma unroll
    for (int ni = 0; ni < 8; ni++)
#pragma unroll
        for (int j = 0; j < 4; j++) acc[ni][j] = 0.f;
    float rs0 = 0.f, rs1 = 0.f;

    const float* Qw  = smf + AOFF_Q + wid * 16 * PK;
    float*       Pw  = smf + AOFF_P + wid * 16 * PP;
    const float* Vsm = smf + AOFF_V;

    for (int t = 0; t < SEQ / 128; t++) {
        // prefetch V_t
        const float* Vt = Vg + (size_t)(t << 7) * DK;
#pragma unroll
        for (int i = 0; i < 8; i++) {
            int f = tid + 256 * i;
            int r = f >> 4;
            int c = (f & 15) << 2;
            cp16(sb + (AOFF_V + r * PV + c) * 4, Vt + (size_t)r * DK + c);
        }
        CP_COMMIT();
        // prefetch K_{t+1}
        if (t + 1 < SEQ / 128) {
            const float* Kt = Kg + (size_t)((t + 1) << 7) * DK;
            const int ko = ((t + 1) & 1) ? AOFF_K1 : AOFF_K0;
#pragma unroll
            for (int i = 0; i < 8; i++) {
                int f = tid + 256 * i;
                int r = f >> 4;
                int c = (f & 15) << 2;
                cp16(sb + (ko + r * PK + c) * 4, Kt + (size_t)r * DK + c);
            }
        }
        CP_COMMIT();

        CP_WAIT(2);                 // K_t (and Q) resident
        __syncthreads();

        const float* Kb = smf + ((t & 1) ? AOFF_K1 : AOFF_K0);

        // ---- scores: 1 m16 x 16 n8 x 8 k8 tf32 mmas ----
        float sc[16][4];
#pragma unroll
        for (int ni = 0; ni < 16; ni++)
#pragma unroll
            for (int j = 0; j < 4; j++) sc[ni][j] = 0.f;

#pragma unroll 4
        for (int k8 = 0; k8 < 8; k8++) {
            const int kc = tq + 8 * k8;
            uint32_t a[4];
            a[0] = cvt_tf32(Qw[g * PK + kc]);
            a[1] = cvt_tf32(Qw[(g + 8) * PK + kc]);
            a[2] = cvt_tf32(Qw[g * PK + kc + 4]);
            a[3] = cvt_tf32(Qw[(g + 8) * PK + kc + 4]);
#pragma unroll
            for (int ni = 0; ni < 16; ni++) {
                uint32_t b[2];
                const float* Kr = Kb + (8 * ni + g) * PK + kc;
                b[0] = cvt_tf32(Kr[0]);
                b[1] = cvt_tf32(Kr[4]);
                mma_tf32(sc[ni], a, b);
            }
        }

        // ---- clip + 2^x on fragments, stage P (warp-private rows) ----
#pragma unroll
        for (int ni = 0; ni < 16; ni++) {
            float e0 = ex2f(fminf(fmaxf(sc[ni][0], -CLIP2), CLIP2));
            float e1 = ex2f(fminf(fmaxf(sc[ni][1], -CLIP2), CLIP2));
            float e2 = ex2f(fminf(fmaxf(sc[ni][2], -CLIP2), CLIP2));
            float e3 = ex2f(fminf(fmaxf(sc[ni][3], -CLIP2), CLIP2));
            rs0 += e0 + e1;
            rs1 += e2 + e3;
            *(float2*)&Pw[g * PP + ni * 8 + 2 * tq]       = make_float2(e0, e1);
            *(float2*)&Pw[(g + 8) * PP + ni * 8 + 2 * tq] = make_float2(e2, e3);
        }

        CP_WAIT(1);                 // V_t resident
        __syncthreads();            // V visible to all warps

        // ---- AV: 1 m16 x 8 n8 x 16 k8 tf32 mmas ----
#pragma unroll 4
        for (int k8 = 0; k8 < 16; k8++) {
            const int kp = tq + 8 * k8;
            uint32_t a[4];
            a[0] = cvt_tf32(Pw[g * PP + kp]);
            a[1] = cvt_tf32(Pw[(g + 8) * PP + kp]);
            a[2] = cvt_tf32(Pw[g * PP + kp + 4]);
            a[3] = cvt_tf32(Pw[(g + 8) * PP + kp + 4]);
#pragma unroll
            for (int ni = 0; ni < 8; ni++) {
                uint32_t b[2];
                b[0] = cvt_tf32(Vsm[kp * PV + 8 * ni + g]);
                b[1] = cvt_tf32(Vsm[(kp + 4) * PV + 8 * ni + g]);
                mma_tf32(acc[ni], a, b);
            }
        }
        __syncthreads();            // V / P reusable next tile
    }

    // ---- quad-reduce rsum (cols partitioned across tq within each quad) ----
    rs0 += __shfl_xor_sync(0xffffffffu, rs0, 1);
    rs0 += __shfl_xor_sync(0xffffffffu, rs0, 2);
    rs1 += __shfl_xor_sync(0xffffffffu, rs1, 1);
    rs1 += __shfl_xor_sync(0xffffffffu, rs1, 2);
    const float inv0 = 1.f / rs0;
    const float inv1 = 1.f / rs1;

    // ---- write ctx in [b,s,h,dk] layout ----
    const int bb = bh >> 4;
    const int h  = bh & 15;
    const int s0 = q0 + wid * 16 + g;
    float* C0 = g_C + (((size_t)(bb * SEQ + s0) * NH + h) << 6);
    float* C1 = C0 + ((size_t)8 * NH << 6);      // row s0 + 8
#pragma unroll
    for (int ni = 0; ni < 8; ni++) {
        *(float2*)&C0[ni * 8 + 2 * tq] = make_float2(acc[ni][0] * inv0,
                                                     acc[ni][1] * inv0);
        *(float2*)&C1[ni * 8 + 2 * tq] = make_float2(acc[ni][2] * inv1,
                                                     acc[ni][3] * inv1);
    }
}

// ===========================================================================
extern "C" void kernel_launch(void* const* d_in, const int* in_sizes, int n_in,
                              void* d_out, int out_size)
{
    const float* X  = (const float*)d_in[0];
    const float* Wq = (const float*)d_in[1];
    const float* Wk = (const float*)d_in[2];
    const float* Wv = (const float*)d_in[3];
    const float* Wo = (const float*)d_in[4];
    float* out = (float*)d_out;

    float *pQ, *pK, *pV, *pC;
    cudaGetSymbolAddress((void**)&pQ, g_Q);
    cudaGetSymbolAddress((void**)&pK, g_K);
    cudaGetSymbolAddress((void**)&pV, g_V);
    cudaGetSymbolAddress((void**)&pC, g_C);

    cudaFuncSetAttribute(gemm_tc<0>, cudaFuncAttributeMaxDynamicSharedMemorySize, GSMEM);
    cudaFuncSetAttribute(gemm_tc<1>, cudaFuncAttributeMaxDynamicSharedMemorySize, GSMEM);
    cudaFuncSetAttribute(attn_tc,    cudaFuncAttributeMaxDynamicSharedMemorySize, ATT_SMEM);

    dim3 gg(DEMB / 128, MTOT / 128);   // (8, 32)
    // Q projection carries 1/sqrt(Dk) * log2(e) so attention can use ex2
    gemm_tc<1><<<gg, 128, GSMEM>>>(X, Wq, pQ, 0.18033688011112042592f);
    gemm_tc<1><<<gg, 128, GSMEM>>>(X, Wk, pK, 1.0f);
    gemm_tc<1><<<gg, 128, GSMEM>>>(X, Wv, pV, 1.0f);

    attn_tc<<<dim3(SEQ / 128, BATCH * NH), 256, ATT_SMEM>>>();

    gemm_tc<0><<<gg, 128, GSMEM>>>(pC, Wo, out, 1.0f);
}

// round 7
// speedup vs baseline: 3.5893x; 1.0780x over previous
#include <cuda_runtime.h>
#include <cstdint>

#define NH    16
#define DK    64
#define BATCH 2
#define SEQ   2048
#define DEMB  1024
#define MTOT  (BATCH*SEQ)   // 4096

// Scratch (allocation-free: device globals)
// g_Q/g_K/g_V hold tf32-PRE-ROUNDED floats (rounded in gemm epilogue);
// g_Q additionally pre-scaled by 0.125*log2(e).
__device__ float g_Q[BATCH*NH*SEQ*DK];
__device__ float g_K[BATCH*NH*SEQ*DK];
__device__ float g_V[BATCH*NH*SEQ*DK];
__device__ float g_C[MTOT*DEMB];         // ctx, [b,s,h,dk] == row-major [4096,1024]

// ---------------------------------------------------------------------------
// helpers
// ---------------------------------------------------------------------------
__device__ __forceinline__ uint32_t smem_u32(const void* p) {
    uint32_t a;
    asm("{ .reg .u64 t; cvta.to.shared.u64 t, %1; cvt.u32.u64 %0, t; }"
        : "=r"(a) : "l"(p));
    return a;
}
__device__ __forceinline__ void cp16(uint32_t dst, const void* src) {
    asm volatile("cp.async.cg.shared.global [%0], [%1], 16;"
                 :: "r"(dst), "l"(src) : "memory");
}
#define CP_COMMIT() asm volatile("cp.async.commit_group;" ::: "memory")
#define CP_WAIT(n)  asm volatile("cp.async.wait_group %0;" :: "n"(n) : "memory")

__device__ __forceinline__ float ex2f(float x) {
    float r; asm("ex2.approx.ftz.f32 %0, %1;" : "=f"(r) : "f"(x)); return r;
}
__device__ __forceinline__ uint32_t cvt_tf32(float x) {
    uint32_t r; asm("cvt.rna.tf32.f32 %0, %1;" : "=r"(r) : "f"(x)); return r;
}
__device__ __forceinline__ void mma_tf32(float* d, const uint32_t* a, const uint32_t* b) {
    asm volatile("mma.sync.aligned.m16n8k8.row.col.f32.tf32.tf32.f32 "
        "{%0,%1,%2,%3}, {%4,%5,%6,%7}, {%8,%9}, {%0,%1,%2,%3};"
        : "+f"(d[0]), "+f"(d[1]), "+f"(d[2]), "+f"(d[3])
        : "r"(a[0]), "r"(a[1]), "r"(a[2]), "r"(a[3]), "r"(b[0]), "r"(b[1]));
}

// ===========================================================================
// tf32 mma.sync GEMM.  MODE 1 epilogue now also tf32-pre-rounds the output
// (numerically identical: attention previously rounded the same values on
// load; rna is idempotent).
// ===========================================================================
#define GPAD 36
#define GSTAGE (2 * 128 * GPAD)
#define GSMEM  (2 * GSTAGE * 4)

template<int MODE>
__global__ void __launch_bounds__(128) gemm_tc(const float* __restrict__ A,
                                               const float* __restrict__ Bm,
                                               float* __restrict__ C,
                                               float cscale)
{
    extern __shared__ float gs[];
    const int tid  = threadIdx.x;
    const int lane = tid & 31;
    const int wid  = tid >> 5;
    const int wm   = (wid & 1) * 64;
    const int wn   = (wid >> 1) * 64;
    const int m0   = blockIdx.y * 128;
    const int n0   = blockIdx.x * 128;
    const uint32_t sb = smem_u32(gs);

#define STAGE_LOAD(cc, ss) do {                                              \
    _Pragma("unroll")                                                        \
    for (int i = 0; i < 16; i++) {                                           \
        int f   = tid + 128 * i;                                             \
        int isB = f >> 10;                                                   \
        int g   = f & 1023;                                                  \
        int row = g >> 3;                                                    \
        int cir = g & 7;                                                     \
        const float* src = (isB ? Bm + (size_t)(n0 + row) * DEMB             \
                                : A  + (size_t)(m0 + row) * DEMB)            \
                           + (cc) * 32 + cir * 4;                            \
        uint32_t dst = sb + ((ss) * GSTAGE + isB * (128 * GPAD)              \
                             + row * GPAD) * 4 + cir * 16;                   \
        cp16(dst, src);                                                      \
    }                                                                        \
} while (0)

    STAGE_LOAD(0, 0); CP_COMMIT();
    STAGE_LOAD(1, 1); CP_COMMIT();

    float acc[4][8][4];
#pragma unroll
    for (int mi = 0; mi < 4; mi++)
#pragma unroll
        for (int ni = 0; ni < 8; ni++)
#pragma unroll
            for (int j = 0; j < 4; j++) acc[mi][ni][j] = 0.f;

    const int r4 = lane >> 2;
    const int c4 = lane & 3;

    for (int c = 0; c < 32; c++) {
        CP_WAIT(1);
        __syncthreads();
        const float* As = gs + (c & 1) * GSTAGE;
        const float* Bs = As + 128 * GPAD;

#pragma unroll
        for (int k8 = 0; k8 < 4; k8++) {
            const int kb = k8 * 8 + c4;
            uint32_t a[4][4], b[8][2];
#pragma unroll
            for (int mi = 0; mi < 4; mi++) {
                const int r = wm + mi * 16 + r4;
                a[mi][0] = cvt_tf32(As[r * GPAD + kb]);
                a[mi][1] = cvt_tf32(As[(r + 8) * GPAD + kb]);
                a[mi][2] = cvt_tf32(As[r * GPAD + kb + 4]);
                a[mi][3] = cvt_tf32(As[(r + 8) * GPAD + kb + 4]);
            }
#pragma unroll
            for (int ni = 0; ni < 8; ni++) {
                const int cn = wn + ni * 8 + r4;
                b[ni][0] = cvt_tf32(Bs[cn * GPAD + kb]);
                b[ni][1] = cvt_tf32(Bs[cn * GPAD + kb + 4]);
            }
#pragma unroll
            for (int mi = 0; mi < 4; mi++)
#pragma unroll
                for (int ni = 0; ni < 8; ni++)
                    mma_tf32(acc[mi][ni], a[mi], b[ni]);
        }
        __syncthreads();
        if (c + 2 < 32) STAGE_LOAD(c + 2, c & 1);
        CP_COMMIT();
    }

    const int c2 = (lane & 3) * 2;
#pragma unroll
    for (int mi = 0; mi < 4; mi++) {
#pragma unroll
        for (int ni = 0; ni < 8; ni++) {
            const int m = m0 + wm + mi * 16 + r4;
            const int n = n0 + wn + ni * 8 + c2;
#pragma unroll
            for (int half = 0; half < 2; half++) {
                const int mm = m + half * 8;
                float2 v = make_float2(acc[mi][ni][2*half]   * cscale,
                                       acc[mi][ni][2*half+1] * cscale);
                if (MODE == 0) {
                    *(float2*)&C[(size_t)mm * DEMB + n] = v;
                } else {
                    v.x = __uint_as_float(cvt_tf32(v.x));   // pre-round for attn
                    v.y = __uint_as_float(cvt_tf32(v.y));
                    const int b  = mm >> 11;
                    const int s  = mm & (SEQ - 1);
                    const int h  = n >> 6;
                    const int dk = n & 63;
                    *(float2*)&C[(((size_t)(b * NH + h) * SEQ + s) << 6) + dk] = v;
                }
            }
        }
    }
#undef STAGE_LOAD
}

// ===========================================================================
// Tensor-core attention v2.
//  - Inputs pre-rounded tf32 -> fragments are raw LDS bits, NO cvt.
//  - Score phase: warp = (mw: m32, kw: 64-k half). K-fragments amortized
//    over 2 m-tiles; per-warp LDS 192 (was 288).
//  - AV phase: warp = (mw: m32, dw: 32-d half). per-warp LDS 256 (was 320).
//  - P written tf32-rounded (used directly by AV mma); rsum partials
//    combined across the two kw-halves via a smem scratch at the end.
// ===========================================================================
#define CLIP2 7.2134752044448169f            // 5 * log2(e)
#define PK 68
#define PV 72
#define PP 132
#define AOFF_Q  0
#define AOFF_K0 (128*PK)
#define AOFF_K1 (2*128*PK)
#define AOFF_V  (3*128*PK)
#define AOFF_P  (3*128*PK + 128*PV)
#define ATT_SMEM ((AOFF_P + 128*PP)*4)       // 208896 bytes

__device__ __forceinline__ uint32_t f2b(float x) { return __float_as_uint(x); }

__global__ void __launch_bounds__(256, 1) attn_tc()
{
    extern __shared__ float smf[];
    const uint32_t sb = smem_u32(smf);
    const int tid  = threadIdx.x;
    const int wid  = tid >> 5;
    const int lane = tid & 31;
    const int g    = lane >> 2;        // row-in-8 group
    const int tq   = lane & 3;         // quad index
    const int mw   = wid & 3;          // m32 block: rows mw*32 .. +31
    const int kw   = wid >> 2;         // score: k-half | AV: d-half
    const int bh   = blockIdx.y;
    const int q0   = blockIdx.x << 7;

    const float* Qg = g_Q + (size_t)bh * (SEQ * DK) + (size_t)q0 * DK;
    const float* Kg = g_K + (size_t)bh * (SEQ * DK);
    const float* Vg = g_V + (size_t)bh * (SEQ * DK);

    // async-load Q tile and K tile 0
#pragma unroll
    for (int i = 0; i < 8; i++) {
        int f = tid + 256 * i;
        int r = f >> 4;
        int c = (f & 15) << 2;
        cp16(sb + (AOFF_Q  + r * PK + c) * 4, Qg + (size_t)r * DK + c);
        cp16(sb + (AOFF_K0 + r * PK + c) * 4, Kg + (size_t)r * DK + c);
    }
    CP_COMMIT();

    float acc[2][4][4];
#pragma unroll
    for (int mi = 0; mi < 2; mi++)
#pragma unroll
        for (int ni = 0; ni < 4; ni++)
#pragma unroll
            for (int j = 0; j < 4; j++) acc[mi][ni][j] = 0.f;
    float rs[4] = {0.f, 0.f, 0.f, 0.f};

    const float* Qw  = smf + AOFF_Q + (mw * 32) * PK;
    float*       Pw  = smf + AOFF_P + (mw * 32) * PP;
    const float* Vsm = smf + AOFF_V;

    for (int t = 0; t < SEQ / 128; t++) {
        // prefetch V_t
        const float* Vt = Vg + (size_t)(t << 7) * DK;
#pragma unroll
        for (int i = 0; i < 8; i++) {
            int f = tid + 256 * i;
            int r = f >> 4;
            int c = (f & 15) << 2;
            cp16(sb + (AOFF_V + r * PV + c) * 4, Vt + (size_t)r * DK + c);
        }
        CP_COMMIT();
        // prefetch K_{t+1}
        if (t + 1 < SEQ / 128) {
            const float* Kt = Kg + (size_t)((t + 1) << 7) * DK;
            const int ko = ((t + 1) & 1) ? AOFF_K1 : AOFF_K0;
#pragma unroll
            for (int i = 0; i < 8; i++) {
                int f = tid + 256 * i;
                int r = f >> 4;
                int c = (f & 15) << 2;
                cp16(sb + (ko + r * PK + c) * 4, Kt + (size_t)r * DK + c);
            }
        }
        CP_COMMIT();

        CP_WAIT(2);                 // K_t (and Q) resident
        __syncthreads();

        // this warp's 64-row half of the K tile
        const float* Kb = smf + ((t & 1) ? AOFF_K1 : AOFF_K0) + (kw * 64) * PK;

        // ---- scores: 2 m16 x 8 n8 x 8 k8 ----
        float sc[2][8][4];
#pragma unroll
        for (int mi = 0; mi < 2; mi++)
#pragma unroll
            for (int ni = 0; ni < 8; ni++)
#pragma unroll
                for (int j = 0; j < 4; j++) sc[mi][ni][j] = 0.f;

#pragma unroll 2
        for (int k8 = 0; k8 < 8; k8++) {
            const int kc = tq + 8 * k8;
            uint32_t a[2][4];
#pragma unroll
            for (int mi = 0; mi < 2; mi++) {
                const float* Qr = Qw + (mi * 16 + g) * PK + kc;
                a[mi][0] = f2b(Qr[0]);
                a[mi][1] = f2b(Qr[8 * PK]);
                a[mi][2] = f2b(Qr[4]);
                a[mi][3] = f2b(Qr[8 * PK + 4]);
            }
#pragma unroll
            for (int ni = 0; ni < 8; ni++) {
                uint32_t b[2];
                const float* Kr = Kb + (8 * ni + g) * PK + kc;
                b[0] = f2b(Kr[0]);
                b[1] = f2b(Kr[4]);
                mma_tf32(sc[0][ni], a[0], b);
                mma_tf32(sc[1][ni], a[1], b);
            }
        }

        // ---- clip + 2^x + tf32-round, stage P cols [kw*64, kw*64+64) ----
#pragma unroll
        for (int mi = 0; mi < 2; mi++) {
            float* Pm = Pw + (mi * 16 + g) * PP + kw * 64 + 2 * tq;
#pragma unroll
            for (int ni = 0; ni < 8; ni++) {
                float e0 = __uint_as_float(cvt_tf32(ex2f(fminf(fmaxf(sc[mi][ni][0], -CLIP2), CLIP2))));
                float e1 = __uint_as_float(cvt_tf32(ex2f(fminf(fmaxf(sc[mi][ni][1], -CLIP2), CLIP2))));
                float e2 = __uint_as_float(cvt_tf32(ex2f(fminf(fmaxf(sc[mi][ni][2], -CLIP2), CLIP2))));
                float e3 = __uint_as_float(cvt_tf32(ex2f(fminf(fmaxf(sc[mi][ni][3], -CLIP2), CLIP2))));
                rs[2 * mi]     += e0 + e1;
                rs[2 * mi + 1] += e2 + e3;
                *(float2*)&Pm[ni * 8]          = make_float2(e0, e1);
                *(float2*)&Pm[ni * 8 + 8 * PP] = make_float2(e2, e3);
            }
        }

        CP_WAIT(1);                 // V_t resident
        __syncthreads();            // all P halves + V visible

        // ---- AV: 2 m16 x 4 n8 (d-half kw) x 16 k8 ----
        const int dcol = kw * 32;
#pragma unroll 2
        for (int k8 = 0; k8 < 16; k8++) {
            const int kp = tq + 8 * k8;
            uint32_t a[2][4];
#pragma unroll
            for (int mi = 0; mi < 2; mi++) {
                const float* Pr = Pw + (mi * 16 + g) * PP + kp;
                a[mi][0] = f2b(Pr[0]);
                a[mi][1] = f2b(Pr[8 * PP]);
                a[mi][2] = f2b(Pr[4]);
                a[mi][3] = f2b(Pr[8 * PP + 4]);
            }
#pragma unroll
            for (int ni = 0; ni < 4; ni++) {
                uint32_t b[2];
                b[0] = f2b(Vsm[kp * PV + dcol + 8 * ni + g]);
                b[1] = f2b(Vsm[(kp + 4) * PV + dcol + 8 * ni + g]);
                mma_tf32(acc[0][ni], a[0], b);
                mma_tf32(acc[1][ni], a[1], b);
            }
        }
        __syncthreads();            // P / V reusable next tile
    }

    // ---- rsum: quad reduce, then combine the two kw halves via smem ----
#pragma unroll
    for (int j = 0; j < 4; j++) {
        rs[j] += __shfl_xor_sync(0xffffffffu, rs[j], 1);
        rs[j] += __shfl_xor_sync(0xffffffffu, rs[j], 2);
    }
    float* Rsum = smf + AOFF_P;     // 256 floats scratch (P no longer needed)
    if (tq == 0) {
        Rsum[kw * 128 + mw * 32 + g]          = rs[0];
        Rsum[kw * 128 + mw * 32 + g + 8]      = rs[1];
        Rsum[kw * 128 + mw * 32 + 16 + g]     = rs[2];
        Rsum[kw * 128 + mw * 32 + 16 + g + 8] = rs[3];
    }
    __syncthreads();

    // ---- normalize + write ctx in [b,s,h,dk] layout ----
    const int bb = bh >> 4;
    const int h  = bh & 15;
#pragma unroll
    for (int mi = 0; mi < 2; mi++) {
        const int r0 = mw * 32 + mi * 16 + g;
        const float inv0 = 1.f / (Rsum[r0]     + Rsum[128 + r0]);
        const float inv1 = 1.f / (Rsum[r0 + 8] + Rsum[128 + r0 + 8]);
        float* C0 = g_C + (((size_t)(bb * SEQ + q0 + r0) * NH + h) << 6) + kw * 32;
        float* C1 = C0 + ((size_t)8 * NH << 6);
#pragma unroll
        for (int ni = 0; ni < 4; ni++) {
            *(float2*)&C0[ni * 8 + 2 * tq] = make_float2(acc[mi][ni][0] * inv0,
                                                         acc[mi][ni][1] * inv0);
            *(float2*)&C1[ni * 8 + 2 * tq] = make_float2(acc[mi][ni][2] * inv1,
                                                         acc[mi][ni][3] * inv1);
        }
    }
}

// ===========================================================================
extern "C" void kernel_launch(void* const* d_in, const int* in_sizes, int n_in,
                              void* d_out, int out_size)
{
    const float* X  = (const float*)d_in[0];
    const float* Wq = (const float*)d_in[1];
    const float* Wk = (const float*)d_in[2];
    const float* Wv = (const float*)d_in[3];
    const float* Wo = (const float*)d_in[4];
    float* out = (float*)d_out;

    float *pQ, *pK, *pV, *pC;
    cudaGetSymbolAddress((void**)&pQ, g_Q);
    cudaGetSymbolAddress((void**)&pK, g_K);
    cudaGetSymbolAddress((void**)&pV, g_V);
    cudaGetSymbolAddress((void**)&pC, g_C);

    cudaFuncSetAttribute(gemm_tc<0>, cudaFuncAttributeMaxDynamicSharedMemorySize, GSMEM);
    cudaFuncSetAttribute(gemm_tc<1>, cudaFuncAttributeMaxDynamicSharedMemorySize, GSMEM);
    cudaFuncSetAttribute(attn_tc,    cudaFuncAttributeMaxDynamicSharedMemorySize, ATT_SMEM);

    dim3 gg(DEMB / 128, MTOT / 128);   // (8, 32)
    // Q projection carries 1/sqrt(Dk) * log2(e) so attention can use ex2
    gemm_tc<1><<<gg, 128, GSMEM>>>(X, Wq, pQ, 0.18033688011112042592f);
    gemm_tc<1><<<gg, 128, GSMEM>>>(X, Wk, pK, 1.0f);
    gemm_tc<1><<<gg, 128, GSMEM>>>(X, Wv, pV, 1.0f);

    attn_tc<<<dim3(SEQ / 128, BATCH * NH), 256, ATT_SMEM>>>();

    gemm_tc<0><<<gg, 128, GSMEM>>>(pC, Wo, out, 1.0f);
}